// round 6
// baseline (speedup 1.0000x reference)
#include <cuda_runtime.h>
#include <cstdint>

#define D_MODEL   1024
#define D_HID     4096
#define NBANKS    16
#define TOKENS    4096
#define ROWS_CAP  12288

// ---------------- device scratch (static: allocation-free) ------------------
__device__ int    g_cnt[NBANKS];
__device__ int    g_cursor[NBANKS];
__device__ int    g_offs[NBANKS];
__device__ int    g_tope[TOKENS * 2];
__device__ float  g_topg[TOKENS * 2];
__device__ int    g_rowtok[ROWS_CAP];
__device__ float  g_rowgate[ROWS_CAP];
__device__ int    g_tokrow[TOKENS * 2];             // token -> its 2 CSR rows
__device__ float  g_Xtf[(size_t)TOKENS * D_MODEL];  // X pre-rounded to tf32 bits
__device__ float  g_H[(size_t)ROWS_CAP * D_HID];    // H scratch (tf32 bits)
__device__ float  g_Y[(size_t)ROWS_CAP * D_MODEL];  // per-row G2 output

// ---------------------------- helpers ---------------------------------------
__device__ __forceinline__ uint32_t smem_u32(const void* p) {
    uint32_t a;
    asm("{ .reg .u64 t; cvta.to.shared.u64 t, %1; cvt.u32.u64 %0, t; }"
        : "=r"(a) : "l"(p));
    return a;
}

__device__ __forceinline__ void cp16(uint32_t dst, const void* src) {
    asm volatile("cp.async.cg.shared.global [%0], [%1], 16;" :: "r"(dst), "l"(src));
}
#define CP_COMMIT() asm volatile("cp.async.commit_group;" ::: "memory")
#define CP_WAIT2()  asm volatile("cp.async.wait_group 2;"  ::: "memory")

// round-to-nearest fp32 -> tf32 (unbiased; truncation would bias ~1e-3)
__device__ __forceinline__ uint32_t f2tf(float f) {
    uint32_t u;
    asm("cvt.rna.tf32.f32 %0, %1;" : "=r"(u) : "f"(f));
    return u;
}

__device__ __forceinline__ void mma8(float d[4], const uint32_t a[4],
                                     const uint32_t b[2]) {
    asm volatile(
        "mma.sync.aligned.m16n8k8.row.col.f32.tf32.tf32.f32 "
        "{%0,%1,%2,%3}, {%4,%5,%6,%7}, {%8,%9}, {%0,%1,%2,%3};"
        : "+f"(d[0]), "+f"(d[1]), "+f"(d[2]), "+f"(d[3])
        : "r"(a[0]), "r"(a[1]), "r"(a[2]), "r"(a[3]), "r"(b[0]), "r"(b[1]));
}

// SMEM geometry (floats). Pads chosen for conflict-free direct-LDS fragments:
//   A_LD=20  -> bank(20g + k) distinct over 32 lanes (all A load phases)
//   B_LD=136 -> bank(8k + g)  distinct over 32 lanes
#define A_LD        20
#define B_LD        136
#define A_STAGE_FL  (128 * A_LD)            // 2560 floats (10240 B)
#define B_STAGE_FL  (16 * B_LD)             // 2176 floats (8704 B)
#define STAGE_FL    (A_STAGE_FL + B_STAGE_FL)
#define STAGE_BYTES (STAGE_FL * 4)          // 18944 B (16B-aligned)
#define SMEM_FLOATS (256 + 4 * STAGE_FL)
#define SMEM_BYTES  (SMEM_FLOATS * 4)       // 76800 B

// ============================================================================
__global__ void zmeta_kernel() {
    int t = threadIdx.x;
    if (t < NBANKS) { g_cnt[t] = 0; g_cursor[t] = 0; }
}

// Pre-round X to tf32 bits (so GEMM1's A fragments need no cvt in mainloop)
__global__ __launch_bounds__(256) void xround_kernel(const float* __restrict__ X) {
    size_t i = ((size_t)blockIdx.x * blockDim.x + threadIdx.x) * 4;
    float4 v = *(const float4*)(X + i);
    float4 o;
    o.x = __uint_as_float(f2tf(v.x));
    o.y = __uint_as_float(f2tf(v.y));
    o.z = __uint_as_float(f2tf(v.z));
    o.w = __uint_as_float(f2tf(v.w));
    *(float4*)(g_Xtf + i) = o;
}

// Router: one warp per token. logits = x.Wr + br, softmax, top-2 probs.
__global__ __launch_bounds__(256) void router_kernel(
    const float* __restrict__ X, const float* __restrict__ Wr,
    const float* __restrict__ br) {
    int gw = (blockIdx.x * blockDim.x + threadIdx.x) >> 5;
    if (gw >= TOKENS) return;
    int lane = threadIdx.x & 31;
    const float* xr = X + (size_t)gw * D_MODEL;

    float acc[NBANKS];
#pragma unroll
    for (int e = 0; e < NBANKS; e++) acc[e] = 0.f;

    for (int i = 0; i < D_MODEL / 32; i++) {
        int k = i * 32 + lane;
        float xv = xr[k];
        const float4* w4 = (const float4*)(Wr + (size_t)k * NBANKS);
#pragma unroll
        for (int q = 0; q < 4; q++) {
            float4 w = w4[q];
            acc[q * 4 + 0] += xv * w.x;
            acc[q * 4 + 1] += xv * w.y;
            acc[q * 4 + 2] += xv * w.z;
            acc[q * 4 + 3] += xv * w.w;
        }
    }
#pragma unroll
    for (int e = 0; e < NBANKS; e++) {
#pragma unroll
        for (int o = 16; o >= 1; o >>= 1)
            acc[e] += __shfl_xor_sync(0xFFFFFFFFu, acc[e], o);
    }
    if (lane != 0) return;
#pragma unroll
    for (int e = 0; e < NBANKS; e++) acc[e] += br[e];

    float m = acc[0];
#pragma unroll
    for (int e = 1; e < NBANKS; e++) m = fmaxf(m, acc[e]);
    float ex[NBANKS], den = 0.f;
#pragma unroll
    for (int e = 0; e < NBANKS; e++) { ex[e] = expf(acc[e] - m); den += ex[e]; }

    // top-2; '>' keeps earliest index on ties, matching lax.top_k order
    int i1 = 0, i2 = -1;
    float v1 = ex[0], v2 = -1.f;
#pragma unroll
    for (int e = 1; e < NBANKS; e++) {
        if (ex[e] > v1)      { v2 = v1; i2 = i1; v1 = ex[e]; i1 = e; }
        else if (ex[e] > v2) { v2 = ex[e]; i2 = e; }
    }
    float inv = 1.f / den;
    g_tope[gw * 2 + 0] = i1; g_topg[gw * 2 + 0] = v1 * inv;
    g_tope[gw * 2 + 1] = i2; g_topg[gw * 2 + 1] = v2 * inv;
    atomicAdd(&g_cnt[i1], 1);
    atomicAdd(&g_cnt[i2], 1);
}

// Padded CSR offsets + padding-row init (pad rows -> token 0, gate 0)
__global__ void offsets_kernel() {
    __shared__ int soff[NBANKS], scnt[NBANKS];
    int tid = threadIdx.x;
    if (tid == 0) {
        int o = 0;
        for (int e = 0; e < NBANKS; e++) {
            int c = g_cnt[e];
            soff[e] = o; scnt[e] = c; g_offs[e] = o;
            o += ((c + 127) >> 7) << 7;
        }
    }
    __syncthreads();
    for (int e = 0; e < NBANKS; e++) {
        int c = scnt[e];
        int pend = ((c + 127) >> 7) << 7;
        for (int i = c + tid; i < pend; i += blockDim.x) {
            g_rowtok[soff[e] + i] = 0;
            g_rowgate[soff[e] + i] = 0.f;
        }
    }
}

// Scatter (token, gate) into bank segments; remember each token's 2 rows.
__global__ void scatter_kernel() {
    int t = blockIdx.x * blockDim.x + threadIdx.x;
    if (t >= TOKENS) return;
#pragma unroll
    for (int j = 0; j < 2; j++) {
        int e = g_tope[t * 2 + j];
        float g = g_topg[t * 2 + j];
        int pos = atomicAdd(&g_cursor[e], 1);
        int r = g_offs[e] + pos;
        g_rowtok[r]  = t;
        g_rowgate[r] = g;
        g_tokrow[t * 2 + j] = r;
    }
}

// ============================================================================
// Grouped GEMM (tf32 mma.sync, 128x128 tile, BK=16, 4-stage cp.async).
//   G1 (IS_G2=false): H = tf32(relu(gather(Xtf) @ W1[e] + b1[e]));  K=1024
//   G2 (IS_G2=true) : Y[row] = gate * (H @ W2[e] + b2[e]);          K=4096
// A operand (g_Xtf / g_H) is pre-rounded tf32 bits -> raw loads, no cvt.
// W layout [e][K][N], N contiguous; bias [e][N].
// ============================================================================
template <int KDEPTH, int LDB, bool IS_G2>
__global__ __launch_bounds__(256, 2) void moe_gemm(
    const float* __restrict__ Abase, const float* __restrict__ W,
    const float* __restrict__ bias) {
    int e = blockIdx.z, nt = blockIdx.y, mt = blockIdx.x;
    int cnt = g_cnt[e];
    if (mt * 128 >= cnt) return;
    int rowbase = g_offs[e] + mt * 128;

    extern __shared__ float sm[];
    float* sgate = sm;                 // [128] gates (G2 only)
    float* stage = sm + 256;

    int t = threadIdx.x, lane = t & 31, wid = t >> 5;
    int wm = wid & 1, wn = wid >> 1;

    if (IS_G2 && t < 128) sgate[t] = g_rowgate[rowbase + t];

    // ---- producer addressing (4 cp.async x 16B per thread per chunk) ----
    int r0 = t >> 2, r1 = 64 + (t >> 2);       // A rows this thread fills
    int aj16 = (t & 3) * 16;
    const float *pa0, *pa1;
    if (!IS_G2) {
        pa0 = Abase + (size_t)g_rowtok[rowbase + r0] * D_MODEL + (t & 3) * 4;
        pa1 = Abase + (size_t)g_rowtok[rowbase + r1] * D_MODEL + (t & 3) * 4;
    } else {
        pa0 = Abase + (size_t)(rowbase + r0) * D_HID + (t & 3) * 4;
        pa1 = Abase + (size_t)(rowbase + r1) * D_HID + (t & 3) * 4;
    }
    const float* Wb = W + (size_t)e * KDEPTH * LDB + (size_t)nt * 128;
    int bkr = t >> 5;                            // B k-row 0..7 (+8 for 2nd)
    int bj16 = (t & 31) * 16;
    const float* pb0 = Wb + (size_t)bkr * LDB + (t & 31) * 4;
    const float* pb1 = pb0 + (size_t)8 * LDB;

    uint32_t sbst = smem_u32(stage);
    uint32_t ar0 = (uint32_t)r0 * (A_LD * 4) + aj16;
    uint32_t ar1 = (uint32_t)r1 * (A_LD * 4) + aj16;
    uint32_t br0 = A_STAGE_FL * 4 + (uint32_t)bkr * (B_LD * 4) + bj16;
    uint32_t br1 = A_STAGE_FL * 4 + (uint32_t)(bkr + 8) * (B_LD * 4) + bj16;

    auto do_load = [&](int s) {
        uint32_t ab = sbst + (uint32_t)s * STAGE_BYTES;
        cp16(ab + ar0, pa0);
        cp16(ab + ar1, pa1);
        cp16(ab + br0, pb0);
        cp16(ab + br1, pb1);
        pa0 += 16; pa1 += 16;
        pb0 += (size_t)16 * LDB; pb1 += (size_t)16 * LDB;
    };

    const int NCH = KDEPTH / 16;
#pragma unroll
    for (int p = 0; p < 3; p++) { do_load(p); CP_COMMIT(); }

    float acc[4][4][4];
#pragma unroll
    for (int a = 0; a < 4; a++)
#pragma unroll
        for (int b = 0; b < 4; b++)
#pragma unroll
            for (int c = 0; c < 4; c++) acc[a][b][c] = 0.f;

#pragma unroll 1
    for (int c = 0; c < NCH; c++) {
        CP_WAIT2();
        __syncthreads();
        const float* As  = stage + (size_t)(c & 3) * STAGE_FL;
        const float* Bsh = As + A_STAGE_FL;
#pragma unroll
        for (int ks = 0; ks < 2; ks++) {
            uint32_t af[4][4], bf[4][2];
            int kb = ks * 8 + (lane & 3);
#pragma unroll
            for (int mi = 0; mi < 4; mi++) {
                const float* ap = As + (wm * 64 + mi * 16 + (lane >> 2)) * A_LD + kb;
                af[mi][0] = __float_as_uint(ap[0]);          // pre-rounded tf32
                af[mi][1] = __float_as_uint(ap[8 * A_LD]);
                af[mi][2] = __float_as_uint(ap[4]);
                af[mi][3] = __float_as_uint(ap[8 * A_LD + 4]);
            }
#pragma unroll
            for (int ni = 0; ni < 4; ni++) {
                const float* bp = Bsh + kb * B_LD + wn * 32 + ni * 8 + (lane >> 2);
                bf[ni][0] = f2tf(bp[0]);
                bf[ni][1] = f2tf(bp[4 * B_LD]);
            }
#pragma unroll
            for (int mi = 0; mi < 4; mi++)
#pragma unroll
                for (int ni = 0; ni < 4; ni++)
                    mma8(acc[mi][ni], af[mi], bf[ni]);
        }
        if (c + 3 < NCH) do_load((c + 3) & 3);
        CP_COMMIT();
    }

    // ---------------------------- epilogue -----------------------------------
    const float* bp = bias + (size_t)e * LDB + (size_t)nt * 128;
#pragma unroll
    for (int mi = 0; mi < 4; mi++) {
#pragma unroll
        for (int ni = 0; ni < 4; ni++) {
            int row = wm * 64 + mi * 16 + (lane >> 2);
            int col = wn * 32 + ni * 8 + 2 * (lane & 3);
            float2 bv = *(const float2*)(bp + col);
            if (!IS_G2) {
                // store relu(acc+b) pre-rounded to tf32 (numerically identical
                // to converting in G2's mainloop; saves cvt there)
                float2 o0, o1;
                o0.x = __uint_as_float(f2tf(fmaxf(acc[mi][ni][0] + bv.x, 0.f)));
                o0.y = __uint_as_float(f2tf(fmaxf(acc[mi][ni][1] + bv.y, 0.f)));
                o1.x = __uint_as_float(f2tf(fmaxf(acc[mi][ni][2] + bv.x, 0.f)));
                o1.y = __uint_as_float(f2tf(fmaxf(acc[mi][ni][3] + bv.y, 0.f)));
                *(float2*)(g_H + (size_t)(rowbase + row) * D_HID +
                           (size_t)nt * 128 + col) = o0;
                *(float2*)(g_H + (size_t)(rowbase + row + 8) * D_HID +
                           (size_t)nt * 128 + col) = o1;
            } else {
                // plain stores into per-row Y (no atomics -> deterministic)
                float g0 = sgate[row], g1 = sgate[row + 8];
                float2 o0, o1;
                o0.x = (acc[mi][ni][0] + bv.x) * g0;
                o0.y = (acc[mi][ni][1] + bv.y) * g0;
                o1.x = (acc[mi][ni][2] + bv.x) * g1;
                o1.y = (acc[mi][ni][3] + bv.y) * g1;
                *(float2*)(g_Y + (size_t)(rowbase + row) * D_MODEL +
                           (size_t)nt * 128 + col) = o0;
                *(float2*)(g_Y + (size_t)(rowbase + row + 8) * D_MODEL +
                           (size_t)nt * 128 + col) = o1;
            }
        }
    }
}

// Combine: out[t] = Y[row0(t)] + Y[row1(t)]  (one block per token)
__global__ __launch_bounds__(256) void combine_kernel(float* __restrict__ out) {
    int t = blockIdx.x;
    int r0 = g_tokrow[t * 2 + 0];
    int r1 = g_tokrow[t * 2 + 1];
    int c = threadIdx.x * 4;
    float4 a = *(const float4*)(g_Y + (size_t)r0 * D_MODEL + c);
    float4 b = *(const float4*)(g_Y + (size_t)r1 * D_MODEL + c);
    float4 o;
    o.x = a.x + b.x; o.y = a.y + b.y; o.z = a.z + b.z; o.w = a.w + b.w;
    *(float4*)(out + (size_t)t * D_MODEL + c) = o;
}

// ============================================================================
extern "C" void kernel_launch(void* const* d_in, const int* in_sizes, int n_in,
                              void* d_out, int out_size) {
    const float* X  = (const float*)d_in[0];
    const float* Wr = (const float*)d_in[1];
    const float* br = (const float*)d_in[2];
    const float* W1 = (const float*)d_in[3];
    const float* b1 = (const float*)d_in[4];
    const float* W2 = (const float*)d_in[5];
    const float* b2 = (const float*)d_in[6];
    float* out = (float*)d_out;

    cudaFuncSetAttribute(moe_gemm<D_MODEL, D_HID, false>,
                         cudaFuncAttributeMaxDynamicSharedMemorySize, SMEM_BYTES);
    cudaFuncSetAttribute(moe_gemm<D_HID, D_MODEL, true>,
                         cudaFuncAttributeMaxDynamicSharedMemorySize, SMEM_BYTES);

    zmeta_kernel<<<1, 32>>>();
    xround_kernel<<<TOKENS * D_MODEL / 1024, 256>>>(X);
    router_kernel<<<TOKENS / 8, 256>>>(X, Wr, br);
    offsets_kernel<<<1, 256>>>();
    scatter_kernel<<<TOKENS / 256, 256>>>();

    float* xtf_dev = nullptr;
    cudaGetSymbolAddress((void**)&xtf_dev, g_Xtf);
    float* h_dev = nullptr;
    cudaGetSymbolAddress((void**)&h_dev, g_H);

    dim3 g1(32, D_HID / 128, NBANKS);     // mt_max x nt x expert
    moe_gemm<D_MODEL, D_HID, false><<<g1, 256, SMEM_BYTES>>>(xtf_dev, W1, b1);
    dim3 g2(32, D_MODEL / 128, NBANKS);
    moe_gemm<D_HID, D_MODEL, true><<<g2, 256, SMEM_BYTES>>>(h_dev, W2, b2);
    combine_kernel<<<TOKENS, 256>>>(out);
}

// round 8
// speedup vs baseline: 1.0177x; 1.0177x over previous
#include <cuda_runtime.h>
#include <cuda_fp16.h>
#include <cstdint>

#define D_MODEL   1024
#define D_HID     4096
#define NBANKS    16
#define TOKENS    4096
#define ROWS_CAP  12288

// ---------------- device scratch (static: allocation-free) ------------------
__device__ int    g_cnt[NBANKS];
__device__ int    g_cursor[NBANKS];
__device__ int    g_offs[NBANKS];
__device__ int    g_tope[TOKENS * 2];
__device__ float  g_topg[TOKENS * 2];
__device__ int    g_rowtok[ROWS_CAP];
__device__ float  g_rowgate[ROWS_CAP];
__device__ int    g_tokrow[TOKENS * 2];              // token -> its 2 CSR rows
__device__ __half g_Xh[(size_t)TOKENS * D_MODEL];    // X in fp16 [tok][k]
__device__ __half g_W1h[(size_t)NBANKS * D_HID * D_MODEL];  // W1^T [e][n][k]
__device__ __half g_W2h[(size_t)NBANKS * D_MODEL * D_HID];  // W2^T [e][n][k]
__device__ __half g_Hh[(size_t)ROWS_CAP * D_HID];    // H in fp16 [row][k]
__device__ float  g_Y[(size_t)ROWS_CAP * D_MODEL];   // per-row G2 output

// ---------------------------- helpers ---------------------------------------
__device__ __forceinline__ uint32_t smem_u32(const void* p) {
    uint32_t a;
    asm("{ .reg .u64 t; cvta.to.shared.u64 t, %1; cvt.u32.u64 %0, t; }"
        : "=r"(a) : "l"(p));
    return a;
}

__device__ __forceinline__ void cp16(uint32_t dst, const void* src) {
    asm volatile("cp.async.cg.shared.global [%0], [%1], 16;" :: "r"(dst), "l"(src));
}
#define CP_COMMIT() asm volatile("cp.async.commit_group;" ::: "memory")
#define CP_WAIT2()  asm volatile("cp.async.wait_group 2;"  ::: "memory")

__device__ __forceinline__ void mma16(float d[4], const uint32_t a[4],
                                      const uint32_t b[2]) {
    asm volatile(
        "mma.sync.aligned.m16n8k16.row.col.f32.f16.f16.f32 "
        "{%0,%1,%2,%3}, {%4,%5,%6,%7}, {%8,%9}, {%0,%1,%2,%3};"
        : "+f"(d[0]), "+f"(d[1]), "+f"(d[2]), "+f"(d[3])
        : "r"(a[0]), "r"(a[1]), "r"(a[2]), "r"(a[3]), "r"(b[0]), "r"(b[1]));
}

// SMEM stage geometry (halfs). Row pad 24 halfs = 12 words:
//   fragment word = 12*(lane>>2) + (lane&3) -> all 32 banks distinct;
//   +8-half (+4 words) and +8-row (+96 words = 0 mod 32) phases shift
//   uniformly -> conflict-free for every load phase.
#define ROW_H       24                         // halfs per SMEM row (16 data + 8 pad)
#define A_STAGE_B   (128 * ROW_H * 2)          // 6144 B
#define STAGE_BYTES (2 * A_STAGE_B)            // 12288 B (A + B)
#define SMEM_BYTES  (1024 + 4 * STAGE_BYTES)   // 50176 B

// ============================================================================
__global__ void zmeta_kernel() {
    int t = threadIdx.x;
    if (t < NBANKS) { g_cnt[t] = 0; g_cursor[t] = 0; }
}

// X fp32 -> fp16 stream
__global__ __launch_bounds__(256) void xconv_kernel(const float* __restrict__ X) {
    size_t i = ((size_t)blockIdx.x * blockDim.x + threadIdx.x) * 4;
    float4 v = *(const float4*)(X + i);
    __half2 h0 = __floats2half2_rn(v.x, v.y);
    __half2 h1 = __floats2half2_rn(v.z, v.w);
    *(__half2*)(g_Xh + i)     = h0;
    *(__half2*)(g_Xh + i + 2) = h1;
}

// W [e][K][N] fp32 -> Wh [e][N][K] fp16 (SMEM-tiled transpose, half2 stores)
__global__ __launch_bounds__(256) void wconv_kernel(
    const float* __restrict__ W, __half* __restrict__ Wh, int K, int N) {
    __shared__ float tile[32][33];
    int e = blockIdx.z;
    int k0 = blockIdx.y * 32, n0 = blockIdx.x * 32;
    int tx = threadIdx.x & 31, ty = threadIdx.x >> 5;   // 32 x 8

    const float* src = W + ((size_t)e * K + k0) * N + n0;
#pragma unroll
    for (int j = 0; j < 4; j++)
        tile[ty + 8 * j][tx] = src[(size_t)(ty + 8 * j) * N + tx];
    __syncthreads();

    __half* dst = Wh + ((size_t)e * N + n0) * K + k0;
    int t = threadIdx.x;
#pragma unroll
    for (int p = 0; p < 2; p++) {
        int q  = t + p * 256;          // 0..511 half2 slots (32 n x 16)
        int nn = q >> 4;
        int kk = (q & 15) * 2;
        __half2 h = __floats2half2_rn(tile[kk][nn], tile[kk + 1][nn]);
        *(__half2*)(dst + (size_t)nn * K + kk) = h;
    }
}

// Router: one warp per token. logits = x.Wr + br, softmax, top-2 probs.
__global__ __launch_bounds__(256) void router_kernel(
    const float* __restrict__ X, const float* __restrict__ Wr,
    const float* __restrict__ br) {
    int gw = (blockIdx.x * blockDim.x + threadIdx.x) >> 5;
    if (gw >= TOKENS) return;
    int lane = threadIdx.x & 31;
    const float* xr = X + (size_t)gw * D_MODEL;

    float acc[NBANKS];
#pragma unroll
    for (int e = 0; e < NBANKS; e++) acc[e] = 0.f;

    for (int i = 0; i < D_MODEL / 32; i++) {
        int k = i * 32 + lane;
        float xv = xr[k];
        const float4* w4 = (const float4*)(Wr + (size_t)k * NBANKS);
#pragma unroll
        for (int q = 0; q < 4; q++) {
            float4 w = w4[q];
            acc[q * 4 + 0] += xv * w.x;
            acc[q * 4 + 1] += xv * w.y;
            acc[q * 4 + 2] += xv * w.z;
            acc[q * 4 + 3] += xv * w.w;
        }
    }
#pragma unroll
    for (int e = 0; e < NBANKS; e++) {
#pragma unroll
        for (int o = 16; o >= 1; o >>= 1)
            acc[e] += __shfl_xor_sync(0xFFFFFFFFu, acc[e], o);
    }
    if (lane != 0) return;
#pragma unroll
    for (int e = 0; e < NBANKS; e++) acc[e] += br[e];

    float m = acc[0];
#pragma unroll
    for (int e = 1; e < NBANKS; e++) m = fmaxf(m, acc[e]);
    float ex[NBANKS], den = 0.f;
#pragma unroll
    for (int e = 0; e < NBANKS; e++) { ex[e] = expf(acc[e] - m); den += ex[e]; }

    int i1 = 0, i2 = -1;
    float v1 = ex[0], v2 = -1.f;
#pragma unroll
    for (int e = 1; e < NBANKS; e++) {
        if (ex[e] > v1)      { v2 = v1; i2 = i1; v1 = ex[e]; i1 = e; }
        else if (ex[e] > v2) { v2 = ex[e]; i2 = e; }
    }
    float inv = 1.f / den;
    g_tope[gw * 2 + 0] = i1; g_topg[gw * 2 + 0] = v1 * inv;
    g_tope[gw * 2 + 1] = i2; g_topg[gw * 2 + 1] = v2 * inv;
    atomicAdd(&g_cnt[i1], 1);
    atomicAdd(&g_cnt[i2], 1);
}

// Padded CSR offsets + padding-row init (pad rows -> token 0, gate 0)
__global__ void offsets_kernel() {
    __shared__ int soff[NBANKS], scnt[NBANKS];
    int tid = threadIdx.x;
    if (tid == 0) {
        int o = 0;
        for (int e = 0; e < NBANKS; e++) {
            int c = g_cnt[e];
            soff[e] = o; scnt[e] = c; g_offs[e] = o;
            o += ((c + 127) >> 7) << 7;
        }
    }
    __syncthreads();
    for (int e = 0; e < NBANKS; e++) {
        int c = scnt[e];
        int pend = ((c + 127) >> 7) << 7;
        for (int i = c + tid; i < pend; i += blockDim.x) {
            g_rowtok[soff[e] + i] = 0;
            g_rowgate[soff[e] + i] = 0.f;
        }
    }
}

__global__ void scatter_kernel() {
    int t = blockIdx.x * blockDim.x + threadIdx.x;
    if (t >= TOKENS) return;
#pragma unroll
    for (int j = 0; j < 2; j++) {
        int e = g_tope[t * 2 + j];
        float g = g_topg[t * 2 + j];
        int pos = atomicAdd(&g_cursor[e], 1);
        int r = g_offs[e] + pos;
        g_rowtok[r]  = t;
        g_rowgate[r] = g;
        g_tokrow[t * 2 + j] = r;
    }
}

// ============================================================================
// Grouped GEMM (fp16 mma m16n8k16, fp32 accum; 128x128 tile, BK=16,
// 4-stage cp.async).  B operand is transposed fp16 weights [e][n][k].
//   G1: Hh = fp16(relu(gather(Xh) @ W1 + b1));  KD=1024, ND=4096
//   G2: Y[row] = gate * (Hh @ W2 + b2);         KD=4096, ND=1024
// ============================================================================
template <int KD, int ND, bool IS_G2>
__global__ __launch_bounds__(256, 2) void moe_gemm(
    const __half* __restrict__ Abase, const __half* __restrict__ Wh,
    const float* __restrict__ bias) {
    int e = blockIdx.z, nt = blockIdx.y, mt = blockIdx.x;
    int cnt = g_cnt[e];
    if (mt * 128 >= cnt) return;
    int rowbase = g_offs[e] + mt * 128;

    extern __shared__ float sm[];
    float* sgate = sm;                  // [128] gates (G2 only)
    char*  stage = (char*)(sm + 256);

    int t = threadIdx.x, lane = t & 31, wid = t >> 5;
    int wm = wid & 1, wn = wid >> 1;

    if (IS_G2 && t < 128) sgate[t] = g_rowgate[rowbase + t];

    // ---- producers: 2 x cp.async 16B per thread per chunk -------------------
    int arow = t >> 1, apart = t & 1;           // A row 0..127, 16B half
    const __half* pa;
    if (!IS_G2)
        pa = Abase + (size_t)g_rowtok[rowbase + arow] * KD + apart * 8;
    else
        pa = Abase + (size_t)(rowbase + arow) * KD + apart * 8;
    // B: n-row 0..127 of this n-tile; Wh row n has KD contiguous halfs
    const __half* pb = Wh + ((size_t)e * ND + (size_t)nt * 128 + arow) * KD
                          + apart * 8;

    uint32_t sbst = smem_u32(stage);
    uint32_t aoff = (uint32_t)arow * (ROW_H * 2) + (uint32_t)apart * 16;
    uint32_t boff = A_STAGE_B + aoff;

    auto do_load = [&](int s) {
        uint32_t ab = sbst + (uint32_t)s * STAGE_BYTES;
        cp16(ab + aoff, pa);
        cp16(ab + boff, pb);
        pa += 16; pb += 16;
    };

    const int NCH = KD / 16;
#pragma unroll
    for (int p = 0; p < 3; p++) { do_load(p); CP_COMMIT(); }

    float acc[4][4][4];
#pragma unroll
    for (int a = 0; a < 4; a++)
#pragma unroll
        for (int b = 0; b < 4; b++)
#pragma unroll
            for (int c = 0; c < 4; c++) acc[a][b][c] = 0.f;

#pragma unroll 1
    for (int c = 0; c < NCH; c++) {
        CP_WAIT2();
        __syncthreads();
        const __half* As = (const __half*)(stage + (size_t)(c & 3) * STAGE_BYTES);
        const __half* Bs = (const __half*)((const char*)As + A_STAGE_B);

        uint32_t af[4][4], bf[4][2];
#pragma unroll
        for (int mi = 0; mi < 4; mi++) {
            const __half* ap = As + (wm * 64 + mi * 16 + (lane >> 2)) * ROW_H
                                  + (lane & 3) * 2;
            af[mi][0] = *(const uint32_t*)ap;
            af[mi][1] = *(const uint32_t*)(ap + 8 * ROW_H);
            af[mi][2] = *(const uint32_t*)(ap + 8);
            af[mi][3] = *(const uint32_t*)(ap + 8 * ROW_H + 8);
        }
#pragma unroll
        for (int ni = 0; ni < 4; ni++) {
            const __half* bp = Bs + (wn * 32 + ni * 8 + (lane >> 2)) * ROW_H
                                  + (lane & 3) * 2;
            bf[ni][0] = *(const uint32_t*)bp;
            bf[ni][1] = *(const uint32_t*)(bp + 8);
        }
#pragma unroll
        for (int mi = 0; mi < 4; mi++)
#pragma unroll
            for (int ni = 0; ni < 4; ni++)
                mma16(acc[mi][ni], af[mi], bf[ni]);

        if (c + 3 < NCH) do_load((c + 3) & 3);
        CP_COMMIT();
    }

    // ---------------------------- epilogue -----------------------------------
    const float* bp = bias + (size_t)e * ND + (size_t)nt * 128;
#pragma unroll
    for (int mi = 0; mi < 4; mi++) {
#pragma unroll
        for (int ni = 0; ni < 4; ni++) {
            int row = wm * 64 + mi * 16 + (lane >> 2);
            int col = wn * 32 + ni * 8 + 2 * (lane & 3);
            float2 bv = *(const float2*)(bp + col);
            if (!IS_G2) {
                __half2 h0 = __floats2half2_rn(
                    fmaxf(acc[mi][ni][0] + bv.x, 0.f),
                    fmaxf(acc[mi][ni][1] + bv.y, 0.f));
                __half2 h1 = __floats2half2_rn(
                    fmaxf(acc[mi][ni][2] + bv.x, 0.f),
                    fmaxf(acc[mi][ni][3] + bv.y, 0.f));
                *(__half2*)(g_Hh + (size_t)(rowbase + row) * D_HID +
                            (size_t)nt * 128 + col) = h0;
                *(__half2*)(g_Hh + (size_t)(rowbase + row + 8) * D_HID +
                            (size_t)nt * 128 + col) = h1;
            } else {
                float g0 = sgate[row], g1 = sgate[row + 8];
                float2 o0, o1;
                o0.x = (acc[mi][ni][0] + bv.x) * g0;
                o0.y = (acc[mi][ni][1] + bv.y) * g0;
                o1.x = (acc[mi][ni][2] + bv.x) * g1;
                o1.y = (acc[mi][ni][3] + bv.y) * g1;
                *(float2*)(g_Y + (size_t)(rowbase + row) * D_MODEL +
                           (size_t)nt * 128 + col) = o0;
                *(float2*)(g_Y + (size_t)(rowbase + row + 8) * D_MODEL +
                           (size_t)nt * 128 + col) = o1;
            }
        }
    }
}

// Combine: out[t] = Y[row0(t)] + Y[row1(t)]  (one block per token)
__global__ __launch_bounds__(256) void combine_kernel(float* __restrict__ out) {
    int t = blockIdx.x;
    int r0 = g_tokrow[t * 2 + 0];
    int r1 = g_tokrow[t * 2 + 1];
    int c = threadIdx.x * 4;
    float4 a = *(const float4*)(g_Y + (size_t)r0 * D_MODEL + c);
    float4 b = *(const float4*)(g_Y + (size_t)r1 * D_MODEL + c);
    float4 o;
    o.x = a.x + b.x; o.y = a.y + b.y; o.z = a.z + b.z; o.w = a.w + b.w;
    *(float4*)(out + (size_t)t * D_MODEL + c) = o;
}

// ============================================================================
extern "C" void kernel_launch(void* const* d_in, const int* in_sizes, int n_in,
                              void* d_out, int out_size) {
    const float* X  = (const float*)d_in[0];
    const float* Wr = (const float*)d_in[1];
    const float* br = (const float*)d_in[2];
    const float* W1 = (const float*)d_in[3];
    const float* b1 = (const float*)d_in[4];
    const float* W2 = (const float*)d_in[5];
    const float* b2 = (const float*)d_in[6];
    float* out = (float*)d_out;

    cudaFuncSetAttribute(moe_gemm<D_MODEL, D_HID, false>,
                         cudaFuncAttributeMaxDynamicSharedMemorySize, SMEM_BYTES);
    cudaFuncSetAttribute(moe_gemm<D_HID, D_MODEL, true>,
                         cudaFuncAttributeMaxDynamicSharedMemorySize, SMEM_BYTES);

    __half *w1h_dev = nullptr, *w2h_dev = nullptr, *xh_dev = nullptr, *hh_dev = nullptr;
    cudaGetSymbolAddress((void**)&w1h_dev, g_W1h);
    cudaGetSymbolAddress((void**)&w2h_dev, g_W2h);
    cudaGetSymbolAddress((void**)&xh_dev,  g_Xh);
    cudaGetSymbolAddress((void**)&hh_dev,  g_Hh);

    zmeta_kernel<<<1, 32>>>();
    xconv_kernel<<<TOKENS * D_MODEL / 1024, 256>>>(X);
    // W1 [e][1024][4096] -> W1h [e][4096][1024]
    wconv_kernel<<<dim3(D_HID / 32, D_MODEL / 32, NBANKS), 256>>>(
        W1, w1h_dev, D_MODEL, D_HID);
    // W2 [e][4096][1024] -> W2h [e][1024][4096]
    wconv_kernel<<<dim3(D_MODEL / 32, D_HID / 32, NBANKS), 256>>>(
        W2, w2h_dev, D_HID, D_MODEL);

    router_kernel<<<TOKENS / 8, 256>>>(X, Wr, br);
    offsets_kernel<<<1, 256>>>();
    scatter_kernel<<<TOKENS / 256, 256>>>();

    dim3 g1(32, D_HID / 128, NBANKS);     // mt_max x nt x expert
    moe_gemm<D_MODEL, D_HID, false><<<g1, 256, SMEM_BYTES>>>(xh_dev, w1h_dev, b1);
    dim3 g2(32, D_MODEL / 128, NBANKS);
    moe_gemm<D_HID, D_MODEL, true><<<g2, 256, SMEM_BYTES>>>(hh_dev, w2h_dev, b2);
    combine_kernel<<<TOKENS, 256>>>(out);
}